// round 13
// baseline (speedup 1.0000x reference)
#include <cuda_runtime.h>
#include <cstdint>

// RecurrentCharLM: B=256, S=32, H=128, VOCAB=256, DEPTH=100, L=1.
// 128 blocks x 128 threads; EACH THREAD serves BOTH batch rows of its block.
// Thread = (col-quad p, k-quarter s2): 4 cols x 32 k per row, W shared
// between rows (128 regs). Row0/row1 FMA streams are independent ILP in one
// instruction stream -> each row's reduce/SHFL latency drains under the
// other row's FMA issue (structural overlap, not scheduler luck).
// One __syncthreads per iteration covers both rows.
// Reduce-scatter across k-quarter lanes (xor 8, xor 16): 3 SHFL/row/thread;
// each lane OWNS one finished column per row -> 1 STS.32 per row.

#define BATCH 256
#define SEQ   32
#define HID   128
#define VOC   256
#define DEPTH_IT 100
#define NBLK  128
#define NTHR  128
#define QP    144          // byte pitch between 32-col segments of h
#define HROW  (4*QP)       // 576 bytes per row buffer

typedef unsigned long long ull;

__device__ __forceinline__ ull pack2(float lo, float hi) {
    ull r; asm("mov.b64 %0, {%1,%2};" : "=l"(r) : "f"(lo), "f"(hi)); return r;
}
__device__ __forceinline__ void unpack2(ull v, float &lo, float &hi) {
    asm("mov.b64 {%0,%1}, %2;" : "=f"(lo), "=f"(hi) : "l"(v));
}
__device__ __forceinline__ ull fma2(ull a, ull b, ull c) {
    ull d; asm("fma.rn.f32x2 %0, %1, %2, %3;" : "=l"(d) : "l"(a), "l"(b), "l"(c));
    return d;
}
__device__ __forceinline__ ull add2(ull a, ull b) {
    ull d; asm("add.rn.f32x2 %0, %1, %2;" : "=l"(d) : "l"(a), "l"(b)); return d;
}
__device__ __forceinline__ ull d2u(double x) { return __double_as_longlong(x); }
__device__ __forceinline__ float red1(ull s) {   // f32x2 -> scalar
    float lo, hi; unpack2(s, lo, hi); return lo + hi;
}

__global__ void __launch_bounds__(NTHR, 1)
rnn_charlm_kernel(const int* __restrict__ chars,
                  const float* __restrict__ hidden,
                  const float* __restrict__ embed_w,
                  const float* __restrict__ Wg,      // (1,128,128): W[k][j]
                  const float* __restrict__ ro_w,    // (256,128)
                  const float* __restrict__ ro_b,    // (256,)
                  float* __restrict__ out, int out_size)
{
    // dynamic smem: ro_w in k-paired transposed layout
    // ro_p[(k>>1)*512 + 2*v + (k&1)] = ro_w[v][k]   (64*512 floats = 128KB)
    extern __shared__ float ro_p[];
    __shared__ __align__(16) char hsraw[2][2][HROW];   // [buf][row][bytes]

    const int tid = threadIdx.x;
    const int w   = tid >> 5;               // warp 0..3
    const int l   = tid & 31;               // lane
    const int s2  = l >> 3;                 // k-quarter 0..3
    const int p   = w * 8 + (l & 7);        // col-quad index 0..31
    const int c0  = 4 * p;                  // first of 4 columns
    const int R0  = blockIdx.x * 2;         // global batch rows
    const int R1  = R0 + 1;
    const int j   = tid;                    // readout col id 0..127
    const int ks  = s2 * 32;                // my k-range start
    // column this lane OWNS after reduce-scatter: s2 0->+0, 1->+2, 2->+1, 3->+3
    const int colown = c0 + ((s2 & 1) << 1) + (s2 >> 1);
    const bool evenq = (s2 & 1) == 0;
    const bool topq  = (s2 & 2) == 0;

    // ---- W: 4 columns x my 32 k's, k-packed (shared by both rows)
    ull wA[16], wB[16], wC[16], wD[16];
#pragma unroll
    for (int i = 0; i < 16; ++i) {
        const float* r0 = &Wg[(ks + 2 * i) * HID];
        const float* r1 = &Wg[(ks + 2 * i + 1) * HID];
        wA[i] = pack2(r0[c0],     r1[c0]);
        wB[i] = pack2(r0[c0 + 1], r1[c0 + 1]);
        wC[i] = pack2(r0[c0 + 2], r1[c0 + 2]);
        wD[i] = pack2(r0[c0 + 3], r1[c0 + 3]);
    }

    // ---- stage ro_w into smem (once)
    for (int idx = tid; idx < VOC * HID; idx += NTHR) {
        int v = idx / HID, k = idx % HID;
        ro_p[(k >> 1) * 512 + 2 * v + (k & 1)] = ro_w[idx];
    }

    float h0 = hidden[R0 * HID + colown];    // owned column, row0
    float h1 = hidden[R1 * HID + colown];    // owned column, row1
    const float rb_lo = ro_b[j];
    const float rb_hi = ro_b[j + 128];
    __syncthreads();   // ro_p staged

    // smem byte address (within a row buffer) of this lane's owned column
    const int ooff = (colown >> 5) * QP + (colown & 31) * 4;

    int cur = 0;
    for (int t = 0; t < SEQ; ++t) {
        // embed add on the owned column (both rows); publish into next buffer
        const int ch0 = chars[R0 * SEQ + t];
        const int ch1 = chars[R1 * SEQ + t];
        h0 += embed_w[ch0 * HID + colown];
        h1 += embed_w[ch1 * HID + colown];
        cur ^= 1;
        *(float*)(hsraw[cur][0] + ooff) = h0;
        *(float*)(hsraw[cur][1] + ooff) = h1;
        __syncthreads();

        // ---- 100 chained relu(h @ W) iterations, both rows fused
        for (int it = 0; it < DEPTH_IT; ++it) {
            const double2* p0 = (const double2*)(hsraw[cur][0] + s2 * QP);
            const double2* p1 = (const double2*)(hsraw[cur][1] + s2 * QP);
            ull aE0 = 0, aO0 = 0, bE0 = 0, bO0 = 0, cE0 = 0, cO0 = 0, dE0 = 0, dO0 = 0;
            ull aE1 = 0, aO1 = 0, bE1 = 0, bO1 = 0, cE1 = 0, cO1 = 0, dE1 = 0, dO1 = 0;
#pragma unroll
            for (int q = 0; q < 8; ++q) {        // 4 k per q, both rows
                double2 x0 = p0[q];
                double2 x1 = p1[q];
                aE0 = fma2(d2u(x0.x), wA[2 * q],     aE0);
                bE0 = fma2(d2u(x0.x), wB[2 * q],     bE0);
                cE0 = fma2(d2u(x0.x), wC[2 * q],     cE0);
                dE0 = fma2(d2u(x0.x), wD[2 * q],     dE0);
                aE1 = fma2(d2u(x1.x), wA[2 * q],     aE1);
                bE1 = fma2(d2u(x1.x), wB[2 * q],     bE1);
                cE1 = fma2(d2u(x1.x), wC[2 * q],     cE1);
                dE1 = fma2(d2u(x1.x), wD[2 * q],     dE1);
                aO0 = fma2(d2u(x0.y), wA[2 * q + 1], aO0);
                bO0 = fma2(d2u(x0.y), wB[2 * q + 1], bO0);
                cO0 = fma2(d2u(x0.y), wC[2 * q + 1], cO0);
                dO0 = fma2(d2u(x0.y), wD[2 * q + 1], dO0);
                aO1 = fma2(d2u(x1.y), wA[2 * q + 1], aO1);
                bO1 = fma2(d2u(x1.y), wB[2 * q + 1], bO1);
                cO1 = fma2(d2u(x1.y), wC[2 * q + 1], cO1);
                dO1 = fma2(d2u(x1.y), wD[2 * q + 1], dO1);
            }
            // ---- reduce-scatter row0 (its SHFL latency drains under row1's work)
            float fA = red1(add2(aE0, aO0));
            float fB = red1(add2(bE0, bO0));
            float fC = red1(add2(cE0, cO0));
            float fD = red1(add2(dE0, dO0));
            float sx0 = evenq ? fC : fA;
            float sy0 = evenq ? fD : fB;
            float rx0 = __shfl_xor_sync(0xffffffffu, sx0, 8);
            float ry0 = __shfl_xor_sync(0xffffffffu, sy0, 8);
            // ---- reduce-scatter row1 round-1 interleaved
            float gA = red1(add2(aE1, aO1));
            float gB = red1(add2(bE1, bO1));
            float gC = red1(add2(cE1, cO1));
            float gD = red1(add2(dE1, dO1));
            float sx1 = evenq ? gC : gA;
            float sy1 = evenq ? gD : gB;
            float rx1 = __shfl_xor_sync(0xffffffffu, sx1, 8);
            float ry1 = __shfl_xor_sync(0xffffffffu, sy1, 8);
            // row0 round-2
            float u0 = (evenq ? fA : fC) + rx0;
            float v0 = (evenq ? fB : fD) + ry0;
            float sz0 = topq ? v0 : u0;
            float rz0 = __shfl_xor_sync(0xffffffffu, sz0, 16);
            // row1 round-2
            float u1 = (evenq ? gA : gC) + rx1;
            float v1 = (evenq ? gB : gD) + ry1;
            float sz1 = topq ? v1 : u1;
            float rz1 = __shfl_xor_sync(0xffffffffu, sz1, 16);
            h0 = fmaxf((topq ? u0 : v0) + rz0, 0.0f);
            h1 = fmaxf((topq ? u1 : v1) + rz1, 0.0f);
            cur ^= 1;
            *(float*)(hsraw[cur][0] + ooff) = h0;
            *(float*)(hsraw[cur][1] + ooff) = h1;
            __syncthreads();
        }

        // ---- readout: logits for both rows, v = j and v = j+128
        {
            const char* hb0 = hsraw[cur][0];
            const char* hb1 = hsraw[cur][1];
            ull P0a = 0, P0b = 0, P1a = 0, P1b = 0;   // row0 lo/hi vocab halves
            ull Q0a = 0, Q0b = 0, Q1a = 0, Q1b = 0;   // row1
#pragma unroll
            for (int q = 0; q < 32; ++q) {       // quad q covers k = 4q..4q+3
                const int boff = (q >> 3) * QP + (q & 7) * 16;
                double2 x0 = *(const double2*)(hb0 + boff);
                double2 x1 = *(const double2*)(hb1 + boff);
                const float* b0 = &ro_p[(2 * q) * 512];
                const float* b1 = &ro_p[(2 * q + 1) * 512];
                ull ra0 = *(const ull*)&b0[2 * j];
                ull rc0 = *(const ull*)&b0[256 + 2 * j];
                ull ra1 = *(const ull*)&b1[2 * j];
                ull rc1 = *(const ull*)&b1[256 + 2 * j];
                P0a = fma2(d2u(x0.x), ra0, P0a);
                P1a = fma2(d2u(x0.x), rc0, P1a);
                P0b = fma2(d2u(x0.y), ra1, P0b);
                P1b = fma2(d2u(x0.y), rc1, P1b);
                Q0a = fma2(d2u(x1.x), ra0, Q0a);
                Q1a = fma2(d2u(x1.x), rc0, Q1a);
                Q0b = fma2(d2u(x1.y), ra1, Q0b);
                Q1b = fma2(d2u(x1.y), rc1, Q1b);
            }
            float lo, hi;
            float* o0 = out + (R0 * SEQ + t) * VOC;
            float* o1 = out + (R1 * SEQ + t) * VOC;
            unpack2(add2(P0a, P0b), lo, hi); o0[j]       = lo + hi + rb_lo;
            unpack2(add2(P1a, P1b), lo, hi); o0[j + 128] = lo + hi + rb_hi;
            unpack2(add2(Q0a, Q0b), lo, hi); o1[j]       = lo + hi + rb_lo;
            unpack2(add2(Q1a, Q1b), lo, hi); o1[j + 128] = lo + hi + rb_hi;
        }
        // next timestep's embed-store targets the OTHER buffer; its barrier
        // orders subsequent writes against these readout reads.
    }

    // ---- h_final (if the harness output includes it after the logits)
    if (out_size >= BATCH * SEQ * VOC + BATCH * HID) {
        float* hf = out + BATCH * SEQ * VOC;
        hf[R0 * HID + colown] = h0;
        hf[R1 * HID + colown] = h1;
    }
}

extern "C" void kernel_launch(void* const* d_in, const int* in_sizes, int n_in,
                              void* d_out, int out_size)
{
    (void)in_sizes; (void)n_in;
    const int*   chars   = (const int*)d_in[0];
    const float* hidden  = (const float*)d_in[1];
    const float* embed_w = (const float*)d_in[2];
    const float* Ws      = (const float*)d_in[3];
    const float* ro_w    = (const float*)d_in[4];
    const float* ro_b    = (const float*)d_in[5];
    float* out = (float*)d_out;

    const size_t smem = 64 * 512 * sizeof(float);   // 128KB dynamic
    cudaFuncSetAttribute(rnn_charlm_kernel,
                         cudaFuncAttributeMaxDynamicSharedMemorySize, (int)smem);
    rnn_charlm_kernel<<<NBLK, NTHR, smem>>>(chars, hidden, embed_w, Ws,
                                            ro_w, ro_b, out, out_size);
}

// round 15
// speedup vs baseline: 1.0736x; 1.0736x over previous
#include <cuda_runtime.h>
#include <cstdint>

// RecurrentCharLM: B=256, S=32, H=128, VOCAB=256, DEPTH=100, L=1.
// R11 architecture (best: 774us): 128 blocks x 256 threads, 2 rows/block,
// thread = (row, col-quad p, k-quarter s2), W 4colsx32k in 128 regs,
// row-scoped named barriers, row1 dephased, reduce-scatter in 3 SHFLs.
// NEW vs R11:
//  * pipelined reduce-scatter: ownership colown = c0+s2 lets round-1 for
//    cols A,B issue right after the A,B FMA block; its SHFL latency drains
//    under the C,D FMA block. Tail after last FMA shrinks ~155 -> ~120 cyc.
//  * explicit 8-load LDS prefetch batch (MLP) at iteration top.
//  * unroll-by-2 over the h double buffer: static src/dst pointers per t.

#define BATCH 256
#define SEQ   32
#define HID   128
#define VOC   256
#define DEPTH_IT 100
#define NBLK  128
#define NTHR  256
#define QP    144          // byte pitch between 32-col segments of h
#define HROW  (4*QP)       // 576 bytes per row buffer

typedef unsigned long long ull;

__device__ __forceinline__ ull pack2(float lo, float hi) {
    ull r; asm("mov.b64 %0, {%1,%2};" : "=l"(r) : "f"(lo), "f"(hi)); return r;
}
__device__ __forceinline__ void unpack2(ull v, float &lo, float &hi) {
    asm("mov.b64 {%0,%1}, %2;" : "=f"(lo), "=f"(hi) : "l"(v));
}
__device__ __forceinline__ ull fma2(ull a, ull b, ull c) {
    ull d; asm("fma.rn.f32x2 %0, %1, %2, %3;" : "=l"(d) : "l"(a), "l"(b), "l"(c));
    return d;
}
__device__ __forceinline__ ull add2(ull a, ull b) {
    ull d; asm("add.rn.f32x2 %0, %1, %2;" : "=l"(d) : "l"(a), "l"(b)); return d;
}
__device__ __forceinline__ ull d2u(double x) { return __double_as_longlong(x); }
__device__ __forceinline__ void row_bar(int id) {
    asm volatile("bar.sync %0, 128;" :: "r"(id) : "memory");
}
__device__ __forceinline__ float red1(ull s) {   // f32x2 -> scalar
    float lo, hi; unpack2(s, lo, hi); return lo + hi;
}

// One recurrence iteration: read h from src (k-quarter s2), produce this
// lane's owned column into dst, row-barrier. Pipelined reduce-scatter:
// round-1(A,B) overlaps the C,D FMA block. Ownership: colown = c0 + s2.
__device__ __forceinline__ float iter_once(
    const char* __restrict__ src, char* __restrict__ dst,
    int s2, int ooff, int bid, bool oddq, bool hiq,
    const ull* __restrict__ wA, const ull* __restrict__ wB,
    const ull* __restrict__ wC, const ull* __restrict__ wD)
{
    const double2* pa = (const double2*)(src + s2 * QP);
    double2 x[8];
#pragma unroll
    for (int q = 0; q < 8; ++q) x[q] = pa[q];          // batched LDS (MLP)

    // ---- FMA block 1: columns A, B
    ull aE = 0, aO = 0, bE = 0, bO = 0;
#pragma unroll
    for (int q = 0; q < 8; ++q) {
        aE = fma2(d2u(x[q].x), wA[2 * q],     aE);
        bE = fma2(d2u(x[q].x), wB[2 * q],     bE);
        aO = fma2(d2u(x[q].y), wA[2 * q + 1], aO);
        bO = fma2(d2u(x[q].y), wB[2 * q + 1], bO);
    }
    float fA = red1(add2(aE, aO));
    float fB = red1(add2(bE, bO));
    float sAB = oddq ? fA : fB;                        // send the non-kept col
    float rAB = __shfl_xor_sync(0xffffffffu, sAB, 8);  // latency drains below

    // ---- FMA block 2: columns C, D (overlaps rAB latency)
    ull cE = 0, cO = 0, dE = 0, dO = 0;
#pragma unroll
    for (int q = 0; q < 8; ++q) {
        cE = fma2(d2u(x[q].x), wC[2 * q],     cE);
        dE = fma2(d2u(x[q].x), wD[2 * q],     dE);
        cO = fma2(d2u(x[q].y), wC[2 * q + 1], cO);
        dO = fma2(d2u(x[q].y), wD[2 * q + 1], dO);
    }
    float fC = red1(add2(cE, cO));
    float fD = red1(add2(dE, dO));
    float sCD = oddq ? fC : fD;
    float rCD = __shfl_xor_sync(0xffffffffu, sCD, 8);

    float h1 = (oddq ? fB : fA) + rAB;   // half-sum of col A (even s2) / B (odd)
    float h2 = (oddq ? fD : fC) + rCD;   // half-sum of col C / D
    // round 2 (xor 16): lo-half lanes keep h1's col, hi-half keep h2's col
    float sv = hiq ? h1 : h2;
    float r2 = __shfl_xor_sync(0xffffffffu, sv, 16);
    float h = fmaxf((hiq ? h2 : h1) + r2, 0.0f);

    *(float*)(dst + ooff) = h;
    row_bar(bid);
    return h;
}

__global__ void __launch_bounds__(NTHR, 1)
rnn_charlm_kernel(const int* __restrict__ chars,
                  const float* __restrict__ hidden,
                  const float* __restrict__ embed_w,
                  const float* __restrict__ Wg,      // (1,128,128): W[k][j]
                  const float* __restrict__ ro_w,    // (256,128)
                  const float* __restrict__ ro_b,    // (256,)
                  float* __restrict__ out, int out_size)
{
    // dynamic smem: ro_w in k-paired transposed layout
    // ro_p[(k>>1)*512 + 2*v + (k&1)] = ro_w[v][k]   (64*512 floats = 128KB)
    extern __shared__ float ro_p[];
    __shared__ __align__(16) char hsraw[2][2][HROW];   // [buf][row][bytes]

    const int tid = threadIdx.x;
    const int row = tid >> 7;               // 0 or 1
    const int w   = (tid >> 5) & 3;         // warp within row
    const int l   = tid & 31;               // lane
    const int s2  = l >> 3;                 // k-quarter 0..3
    const int p   = w * 8 + (l & 7);        // col-quad index 0..31
    const int c0  = 4 * p;                  // first of 4 columns
    const int R   = blockIdx.x * 2 + row;   // global batch row
    const int j   = w * 32 + l;             // readout col id 0..127
    const int ks  = s2 * 32;                // my k-range start
    const int bid = 1 + row;                // named barrier id
    const int colown = c0 + s2;             // owned column after reduce-scatter
    const bool oddq = (s2 & 1) != 0;
    const bool hiq  = (s2 & 2) != 0;

    // ---- W: 4 columns x my 32 k's, k-packed
    ull wA[16], wB[16], wC[16], wD[16];
#pragma unroll
    for (int i = 0; i < 16; ++i) {
        const float* r0 = &Wg[(ks + 2 * i) * HID];
        const float* r1 = &Wg[(ks + 2 * i + 1) * HID];
        wA[i] = pack2(r0[c0],     r1[c0]);
        wB[i] = pack2(r0[c0 + 1], r1[c0 + 1]);
        wC[i] = pack2(r0[c0 + 2], r1[c0 + 2]);
        wD[i] = pack2(r0[c0 + 3], r1[c0 + 3]);
    }

    // ---- stage ro_w into smem (once)
    for (int idx = tid; idx < VOC * HID; idx += NTHR) {
        int v = idx / HID, k = idx % HID;
        ro_p[(k >> 1) * 512 + 2 * v + (k & 1)] = ro_w[idx];
    }

    float hval = hidden[R * HID + colown];       // this lane's owned column
    const float rb_lo = ro_b[j];
    const float rb_hi = ro_b[j + 128];
    __syncthreads();   // ro_p staged

    // ---- SYMMETRY BREAKER: row1 delayed ~240 cyc (exact-identity chain)
    if (row == 1) {
        const float one = __int_as_float(0x3f800000);
        float d = hval;
#pragma unroll
        for (int i = 0; i < 60; ++i)
            asm volatile("mul.f32 %0, %0, %1;" : "+f"(d) : "f"(one));
        hval = d;
    }

    // smem byte address (within a row buffer) of this lane's owned column
    const int ooff = (colown >> 5) * QP + (colown & 31) * 4;

    int cur = 0;
    for (int t = 0; t < SEQ; ++t) {
        // embed add on the owned column; publish into next buffer
        const int c = chars[R * SEQ + t];
        hval += embed_w[c * HID + colown];
        cur ^= 1;
        char* bufA = hsraw[cur][row];
        char* bufB = hsraw[cur ^ 1][row];
        *(float*)(bufA + ooff) = hval;
        row_bar(bid);

        // ---- 100 chained relu(h @ W) iterations, unrolled x2 (static bufs)
        for (int it = 0; it < DEPTH_IT / 2; ++it) {
            hval = iter_once(bufA, bufB, s2, ooff, bid, oddq, hiq, wA, wB, wC, wD);
            hval = iter_once(bufB, bufA, s2, ooff, bid, oddq, hiq, wA, wB, wC, wD);
        }
        // after an even number of iterations h is back in bufA

        // ---- readout: logits[R][v] for v = j and v = j+128
        {
            const char* hb = bufA;
            ull A0a = 0, A0b = 0, A1a = 0, A1b = 0;
#pragma unroll
            for (int q = 0; q < 32; ++q) {       // quad q covers k = 4q..4q+3
                double2 x = *(const double2*)(hb + (q >> 3) * QP + (q & 7) * 16);
                const float* b0 = &ro_p[(2 * q) * 512];
                const float* b1 = &ro_p[(2 * q + 1) * 512];
                ull ra0 = *(const ull*)&b0[2 * j];
                ull rc0 = *(const ull*)&b0[256 + 2 * j];
                ull ra1 = *(const ull*)&b1[2 * j];
                ull rc1 = *(const ull*)&b1[256 + 2 * j];
                A0a = fma2(d2u(x.x), ra0, A0a);
                A1a = fma2(d2u(x.x), rc0, A1a);
                A0b = fma2(d2u(x.y), ra1, A0b);
                A1b = fma2(d2u(x.y), rc1, A1b);
            }
            float lo, hi;
            float* o = out + (R * SEQ + t) * VOC;
            ull A0 = add2(A0a, A0b);
            ull A1 = add2(A1a, A1b);
            unpack2(A0, lo, hi); o[j]       = lo + hi + rb_lo;
            unpack2(A1, lo, hi); o[j + 128] = lo + hi + rb_hi;
        }
        // next timestep's embed-store targets the OTHER buffer; its row barrier
        // orders subsequent in-loop writes against these readout reads.
    }

    // ---- h_final (if the harness output includes it after the logits)
    if (out_size >= BATCH * SEQ * VOC + BATCH * HID) {
        float* hf = out + BATCH * SEQ * VOC;
        hf[R * HID + colown] = hval;
    }
}

extern "C" void kernel_launch(void* const* d_in, const int* in_sizes, int n_in,
                              void* d_out, int out_size)
{
    (void)in_sizes; (void)n_in;
    const int*   chars   = (const int*)d_in[0];
    const float* hidden  = (const float*)d_in[1];
    const float* embed_w = (const float*)d_in[2];
    const float* Ws      = (const float*)d_in[3];
    const float* ro_w    = (const float*)d_in[4];
    const float* ro_b    = (const float*)d_in[5];
    float* out = (float*)d_out;

    const size_t smem = 64 * 512 * sizeof(float);   // 128KB dynamic
    cudaFuncSetAttribute(rnn_charlm_kernel,
                         cudaFuncAttributeMaxDynamicSharedMemorySize, (int)smem);
    rnn_charlm_kernel<<<NBLK, NTHR, smem>>>(chars, hidden, embed_w, Ws,
                                            ro_w, ro_b, out, out_size);
}